// round 1
// baseline (speedup 1.0000x reference)
#include <cuda_runtime.h>
#include <math.h>

// Problem constants (fixed by the reference: B=8, T=2048, C=1024, H=16, d=64)
#define B_  8
#define T_  2048
#define C_  1024
#define H_  16
#define D_  64

// Scratch for q/k/v in (B,H,T,d) layout. 3 x 64 MB static device globals
// (allocation-free per harness rules).
__device__ float g_q[B_ * H_ * T_ * D_];
__device__ float g_k[B_ * H_ * T_ * D_];
__device__ float g_v[B_ * H_ * T_ * D_];

// ---------------------------------------------------------------------------
// Kernel 1: fused QKV projection GEMM.
//   qkv[m][n] = x[m][:] . W[:][n] + b[n],  M=16384, N=3072, K=1024
// Output scattered directly into g_q/g_k/g_v in (B,H,T,d) layout.
// 128x128 block tile, BK=16, 256 threads, 8x8 per thread (split 2x2 of 4x4
// so shared reads are LDS.128 with minimal wavefronts).
// ---------------------------------------------------------------------------
__global__ __launch_bounds__(256, 2)
void qkv_gemm_kernel(const float* __restrict__ X,
                     const float* __restrict__ W,
                     const float* __restrict__ bias)
{
    __shared__ float As[16][128];   // A tile, k-major (transposed on store)
    __shared__ float Bs[16][128];   // B tile, natural

    const int tid = threadIdx.x;
    const int tx  = tid & 15;
    const int ty  = tid >> 4;
    const int n0  = blockIdx.x * 128;
    const int m0  = blockIdx.y * 128;

    float acc[8][8];
#pragma unroll
    for (int i = 0; i < 8; ++i)
#pragma unroll
        for (int j = 0; j < 8; ++j) acc[i][j] = 0.f;

    for (int k0 = 0; k0 < 1024; k0 += 16) {
        // Load A 128x16 (transposed into As[k][m])
#pragma unroll
        for (int it = 0; it < 2; ++it) {
            int f   = tid * 2 + it;        // 0..511 float4 ids
            int row = f >> 2;              // 0..127
            int cc  = (f & 3) << 2;        // 0,4,8,12
            float4 v = *(const float4*)(X + (m0 + row) * 1024 + k0 + cc);
            As[cc + 0][row] = v.x;
            As[cc + 1][row] = v.y;
            As[cc + 2][row] = v.z;
            As[cc + 3][row] = v.w;
        }
        // Load B 16x128 (natural, coalesced)
#pragma unroll
        for (int it = 0; it < 2; ++it) {
            int f = tid * 2 + it;          // 0..511
            int r = f >> 5;                // 0..15
            int c = (f & 31) << 2;         // 0..124
            *(float4*)&Bs[r][c] = *(const float4*)(W + (k0 + r) * 3072 + n0 + c);
        }
        __syncthreads();

#pragma unroll
        for (int k = 0; k < 16; ++k) {
            float a[8], bb[8];
            *(float4*)(a)      = *(float4*)&As[k][ty * 4];
            *(float4*)(a + 4)  = *(float4*)&As[k][64 + ty * 4];
            *(float4*)(bb)     = *(float4*)&Bs[k][tx * 4];
            *(float4*)(bb + 4) = *(float4*)&Bs[k][64 + tx * 4];
#pragma unroll
            for (int i = 0; i < 8; ++i)
#pragma unroll
                for (int j = 0; j < 8; ++j)
                    acc[i][j] = fmaf(a[i], bb[j], acc[i][j]);
        }
        __syncthreads();
    }

    // Epilogue: add bias, scatter into (B,H,T,d) layout of q/k/v.
#pragma unroll
    for (int i = 0; i < 8; ++i) {
        int gm = m0 + ((i & 4) << 4) + ty * 4 + (i & 3);  // global row (b*T + t)
        int b  = gm >> 11;
        int t  = gm & 2047;
#pragma unroll
        for (int j = 0; j < 8; ++j) {
            int gn = n0 + ((j & 4) << 4) + tx * 4 + (j & 3);  // global col in 3C
            float val = acc[i][j] + bias[gn];
            int which = gn >> 10;          // 0=q, 1=k, 2=v
            int cidx  = gn & 1023;
            int h     = cidx >> 6;
            int dd    = cidx & 63;
            float* dst = (which == 0) ? g_q : ((which == 1) ? g_k : g_v);
            dst[(((b << 4) + h) * 2048 + t) * 64 + dd] = val;
        }
    }
}

// ---------------------------------------------------------------------------
// Kernel 2: flash attention over g_q/g_k/g_v (one (b,h) per blockIdx.y,
// BM=64 query rows per CTA, BN=64 keys per inner iteration, d=64).
// Online softmax; masked keys get -inf scores (exp underflows to exactly 0).
// Output written with the reference's "no transpose back" reshape:
//   (B,H,T,d) flat -> (B,T,C):  t_out = h*128 + t/16, c_out = (t%16)*64 + dd
// ---------------------------------------------------------------------------
#define PITCH 68   // shared row pitch: multiple of 4 (float4 align), not mult of 32
#define FLASH_SMEM_BYTES ((64 * PITCH * 3 + 64 * 64) * 4 + 64 * 4)

__global__ __launch_bounds__(256)
void flash_attn_kernel(const int* __restrict__ mask, float* __restrict__ out)
{
    extern __shared__ float sm[];
    float* Qs = sm;                    // [64][PITCH] d-major (transposed), pre-scaled
    float* Ks = Qs + 64 * PITCH;       // [64][PITCH] d-major (transposed)
    float* Ps = Ks + 64 * PITCH;       // [64][PITCH] key-major probabilities
    float* Vs = Ps + 64 * PITCH;       // [64][64]    key-major, natural
    int*   Ms = (int*)(Vs + 64 * 64);  // [64] key mask

    const int tid = threadIdx.x;
    const int tx  = tid & 15;
    const int ty  = tid >> 4;
    const int bh  = blockIdx.y;
    const int b   = bh >> 4;
    const int h   = bh & 15;
    const int q0  = blockIdx.x * 64;
    const int base = bh * (T_ * D_);

    // Load Q tile once, transposed (d-major), with 1/sqrt(d)=0.125 folded in.
#pragma unroll
    for (int it = 0; it < 4; ++it) {
        int f   = tid * 4 + it;        // 0..1023 float4 ids
        int row = f >> 4;              // query row 0..63
        int c   = (f & 15) << 2;       // d offset
        float4 v = *(const float4*)(g_q + base + (q0 + row) * 64 + c);
        Qs[(c + 0) * PITCH + row] = v.x * 0.125f;
        Qs[(c + 1) * PITCH + row] = v.y * 0.125f;
        Qs[(c + 2) * PITCH + row] = v.z * 0.125f;
        Qs[(c + 3) * PITCH + row] = v.w * 0.125f;
    }

    float m_i[4], l_i[4], acc[4][4];
#pragma unroll
    for (int i = 0; i < 4; ++i) {
        m_i[i] = -1e30f;
        l_i[i] = 0.f;
#pragma unroll
        for (int j = 0; j < 4; ++j) acc[i][j] = 0.f;
    }

    for (int kb = 0; kb < T_; kb += 64) {
        __syncthreads();   // previous PV done reading Ps/Vs; Q load visible

        // Load K (transposed, d-major) and V (natural) tiles + mask slice
#pragma unroll
        for (int it = 0; it < 4; ++it) {
            int f   = tid * 4 + it;
            int row = f >> 4;
            int c   = (f & 15) << 2;
            float4 v = *(const float4*)(g_k + base + (kb + row) * 64 + c);
            Ks[(c + 0) * PITCH + row] = v.x;
            Ks[(c + 1) * PITCH + row] = v.y;
            Ks[(c + 2) * PITCH + row] = v.z;
            Ks[(c + 3) * PITCH + row] = v.w;
            float4 w = *(const float4*)(g_v + base + (kb + row) * 64 + c);
            *(float4*)&Vs[row * 64 + c] = w;
        }
        if (tid < 64) Ms[tid] = mask[b * T_ + kb + tid];
        __syncthreads();

        // S = Q . K^T   (scale already folded into Q)
        float s[4][4];
#pragma unroll
        for (int i = 0; i < 4; ++i)
#pragma unroll
            for (int j = 0; j < 4; ++j) s[i][j] = 0.f;
#pragma unroll
        for (int k = 0; k < 64; ++k) {
            float a[4], bb[4];
            *(float4*)a  = *(float4*)&Qs[k * PITCH + ty * 4];
            *(float4*)bb = *(float4*)&Ks[k * PITCH + tx * 4];
#pragma unroll
            for (int i = 0; i < 4; ++i)
#pragma unroll
                for (int j = 0; j < 4; ++j)
                    s[i][j] = fmaf(a[i], bb[j], s[i][j]);
        }

        // Mask: key==0 -> -inf (exp gives exact 0; m_i stays floored at -1e30)
#pragma unroll
        for (int j = 0; j < 4; ++j) {
            if (Ms[tx * 4 + j] == 0) {
#pragma unroll
                for (int i = 0; i < 4; ++i) s[i][j] = -INFINITY;
            }
        }

        // Online softmax update (row stats reduced across the 16 tx lanes)
#pragma unroll
        for (int i = 0; i < 4; ++i) {
            float rm = fmaxf(fmaxf(s[i][0], s[i][1]), fmaxf(s[i][2], s[i][3]));
#pragma unroll
            for (int off = 8; off >= 1; off >>= 1)
                rm = fmaxf(rm, __shfl_xor_sync(0xffffffffu, rm, off));
            float mn = fmaxf(m_i[i], rm);
            float sc = __expf(m_i[i] - mn);
            m_i[i] = mn;
            l_i[i] *= sc;
#pragma unroll
            for (int j = 0; j < 4; ++j) acc[i][j] *= sc;

            float rs = 0.f;
#pragma unroll
            for (int j = 0; j < 4; ++j) {
                float p = __expf(s[i][j] - mn);
                s[i][j] = p;
                rs += p;
            }
#pragma unroll
            for (int off = 8; off >= 1; off >>= 1)
                rs += __shfl_xor_sync(0xffffffffu, rs, off);
            l_i[i] += rs;
        }

        // Store P transposed [key][query] as float4 over the 4 query rows
#pragma unroll
        for (int j = 0; j < 4; ++j) {
            float4 p4 = make_float4(s[0][j], s[1][j], s[2][j], s[3][j]);
            *(float4*)&Ps[(tx * 4 + j) * PITCH + ty * 4] = p4;
        }
        __syncthreads();

        // acc += P . V
#pragma unroll
        for (int k = 0; k < 64; ++k) {
            float a[4], bb[4];
            *(float4*)a  = *(float4*)&Ps[k * PITCH + ty * 4];
            *(float4*)bb = *(float4*)&Vs[k * 64 + tx * 4];
#pragma unroll
            for (int i = 0; i < 4; ++i)
#pragma unroll
                for (int j = 0; j < 4; ++j)
                    acc[i][j] = fmaf(a[i], bb[j], acc[i][j]);
        }
    }

    // Normalize and write with the reference's (B,H,T,d)->(B,T,C) flat reshape
#pragma unroll
    for (int i = 0; i < 4; ++i) {
        int qi     = q0 + ty * 4 + i;
        int t_out  = h * 128 + (qi >> 4);
        int c_base = (qi & 15) << 6;
        float inv  = 1.f / l_i[i];
#pragma unroll
        for (int j = 0; j < 4; ++j) {
            out[(b * T_ + t_out) * C_ + c_base + tx * 4 + j] = acc[i][j] * inv;
        }
    }
}

// ---------------------------------------------------------------------------
// Launch: inputs per metadata order: x (f32), mask (i32), W_qkv (f32), b_qkv (f32)
// ---------------------------------------------------------------------------
extern "C" void kernel_launch(void* const* d_in, const int* in_sizes, int n_in,
                              void* d_out, int out_size)
{
    const float* x    = (const float*)d_in[0];
    const int*   mask = (const int*)d_in[1];
    const float* W    = (const float*)d_in[2];
    const float* bq   = (const float*)d_in[3];
    float*       out  = (float*)d_out;

    // Opt-in to >48KB dynamic shared for the flash kernel (idempotent, no sync,
    // graph-capture safe: executes immediately, enqueues nothing).
    cudaFuncSetAttribute(flash_attn_kernel,
                         cudaFuncAttributeMaxDynamicSharedMemorySize,
                         FLASH_SMEM_BYTES);

    dim3 g1(3072 / 128, 16384 / 128);   // (N tiles, M tiles)
    qkv_gemm_kernel<<<g1, 256>>>(x, W, bq);

    dim3 g2(T_ / 64, B_ * H_);          // (query tiles, b*h)
    flash_attn_kernel<<<g2, 256, FLASH_SMEM_BYTES>>>(mask, out);
}

// round 5
// speedup vs baseline: 3.2806x; 3.2806x over previous
#include <cuda_runtime.h>
#include <math.h>
#include <stdint.h>

// Problem constants (B=8, T=2048, C=1024, H=16, d=64)
#define B_  8
#define T_  2048
#define C_  1024
#define H_  16
#define D_  64
#define M_TOT 16384
#define N_TOT 3072
#define K_TOT 1024

// q/k/v scratch in (B,H,T,d) layout (as in the passing R1 kernel)
__device__ float g_q[B_ * H_ * T_ * D_];
__device__ float g_k[B_ * H_ * T_ * D_];
__device__ float g_v[B_ * H_ * T_ * D_];

// ---------------------------------------------------------------------------
// Helpers: tf32 mma.sync (compute_100-safe, sm_80+ features only)
// ---------------------------------------------------------------------------
__device__ __forceinline__ uint32_t cvt_tf32(float x) {
    uint32_t r;
    asm("cvt.rna.tf32.f32 %0, %1;" : "=r"(r) : "f"(x));
    return r;
}

// D += A(16x8) * B(8x8), tf32 inputs, f32 accumulate.
__device__ __forceinline__ void mma_tf32(float* d, const uint32_t* a,
                                         uint32_t b0, uint32_t b1) {
    asm volatile(
        "mma.sync.aligned.m16n8k8.row.col.f32.tf32.tf32.f32 "
        "{%0,%1,%2,%3}, {%4,%5,%6,%7}, {%8,%9}, {%0,%1,%2,%3};"
        : "+f"(d[0]), "+f"(d[1]), "+f"(d[2]), "+f"(d[3])
        : "r"(a[0]), "r"(a[1]), "r"(a[2]), "r"(a[3]), "r"(b0), "r"(b1));
}

__device__ __forceinline__ uint32_t smem_u32(const void* p) {
    uint32_t a;
    asm("{ .reg .u64 t; cvta.to.shared.u64 t, %1; cvt.u32.u64 %0, t; }"
        : "=r"(a) : "l"(p));
    return a;
}
__device__ __forceinline__ void cp16(uint32_t s, const void* g) {
    asm volatile("cp.async.cg.shared.global [%0], [%1], 16;" :: "r"(s), "l"(g));
}
#define CP_COMMIT() asm volatile("cp.async.commit_group;" ::: "memory")
#define CP_WAIT0()  asm volatile("cp.async.wait_group 0;" ::: "memory")
#define CP_WAIT1()  asm volatile("cp.async.wait_group 1;" ::: "memory")

// ---------------------------------------------------------------------------
// Kernel 1: QKV GEMM via mma.sync tf32.
// CTA 128x128, BK=32, 8 warps as 2(m) x 4(n) -> warp tile 64x32.
// SMEM pitches: A[m][k] pitch 36 (=4 mod 32), B[k][n] pitch 136 (=8 mod 32):
// all fragment LDS patterns bank-conflict-free.
// ---------------------------------------------------------------------------
#define APITCH 36
#define BPITCH 136
#define ASZ (128 * APITCH)     // 4608 floats
#define BSZ (32 * BPITCH)      // 4352 floats
#define GEMM_SMEM_BYTES ((2 * ASZ + 2 * BSZ) * 4)

__device__ __forceinline__ void gemm_stage(float* A, float* Bx,
                                           const float* __restrict__ X,
                                           const float* __restrict__ W,
                                           int m0, int n0, int k0, int tid,
                                           uint32_t sA, uint32_t sB)
{
#pragma unroll
    for (int it = 0; it < 4; ++it) {          // A: 128 rows x 32 floats
        int f   = it * 256 + tid;
        int row = f >> 3;
        int seg = f & 7;
        cp16(sA + (row * APITCH + seg * 4) * 4,
             X + (size_t)(m0 + row) * K_TOT + k0 + seg * 4);
    }
#pragma unroll
    for (int it = 0; it < 4; ++it) {          // B: 32 rows x 128 floats
        int f   = it * 256 + tid;
        int row = f >> 5;
        int seg = f & 31;
        cp16(sB + (row * BPITCH + seg * 4) * 4,
             W + (size_t)(k0 + row) * N_TOT + n0 + seg * 4);
    }
}

__global__ __launch_bounds__(256)
void qkv_gemm_mma(const float* __restrict__ X, const float* __restrict__ W,
                  const float* __restrict__ bias)
{
    extern __shared__ float sm[];
    float* A0 = sm;
    float* A1 = sm + ASZ;
    float* B0 = sm + 2 * ASZ;
    float* B1 = B0 + BSZ;

    const int tid  = threadIdx.x;
    const int wid  = tid >> 5;
    const int lane = tid & 31;
    const int gid  = lane >> 2;
    const int tig  = lane & 3;
    const int n0   = blockIdx.x * 128;
    const int m0   = blockIdx.y * 128;
    const int warp_m = (wid >> 2) * 64;
    const int warp_n = (wid & 3) * 32;

    const uint32_t sA0 = smem_u32(A0), sA1 = smem_u32(A1);
    const uint32_t sB0 = smem_u32(B0), sB1 = smem_u32(B1);

    float acc[4][4][4];
#pragma unroll
    for (int mi = 0; mi < 4; ++mi)
#pragma unroll
        for (int ni = 0; ni < 4; ++ni)
#pragma unroll
            for (int r = 0; r < 4; ++r) acc[mi][ni][r] = 0.f;

    gemm_stage(A0, B0, X, W, m0, n0, 0, tid, sA0, sB0);
    CP_COMMIT();

    for (int it = 0; it < 32; ++it) {
        if (it < 31) {
            gemm_stage((it & 1) ? A0 : A1, (it & 1) ? B0 : B1, X, W,
                       m0, n0, (it + 1) * 32, tid,
                       (it & 1) ? sA0 : sA1, (it & 1) ? sB0 : sB1);
            CP_COMMIT();
            CP_WAIT1();
        } else {
            CP_WAIT0();
        }
        __syncthreads();

        const float* A = (it & 1) ? A1 : A0;
        const float* B = (it & 1) ? B1 : B0;

#pragma unroll
        for (int s = 0; s < 4; ++s) {         // 4 ksteps of k=8
            uint32_t af[4][4];
#pragma unroll
            for (int mi = 0; mi < 4; ++mi) {
                int r0 = warp_m + mi * 16 + gid;
                int kc = s * 8 + tig;
                af[mi][0] = cvt_tf32(A[r0 * APITCH + kc]);
                af[mi][1] = cvt_tf32(A[(r0 + 8) * APITCH + kc]);
                af[mi][2] = cvt_tf32(A[r0 * APITCH + kc + 4]);
                af[mi][3] = cvt_tf32(A[(r0 + 8) * APITCH + kc + 4]);
            }
            uint32_t bf[4][2];
#pragma unroll
            for (int ni = 0; ni < 4; ++ni) {
                int nc = warp_n + ni * 8 + gid;
                int kc = s * 8 + tig;
                bf[ni][0] = cvt_tf32(B[kc * BPITCH + nc]);
                bf[ni][1] = cvt_tf32(B[(kc + 4) * BPITCH + nc]);
            }
#pragma unroll
            for (int mi = 0; mi < 4; ++mi)
#pragma unroll
                for (int ni = 0; ni < 4; ++ni)
                    mma_tf32(acc[mi][ni], af[mi], bf[ni][0], bf[ni][1]);
        }
        __syncthreads();
    }

    // Epilogue: add bias, scatter float2 into g_q/g_k/g_v (B,H,T,d)
#pragma unroll
    for (int mi = 0; mi < 4; ++mi) {
        int m = m0 + warp_m + mi * 16 + gid;
        int b = m >> 11;
        int t = m & 2047;
#pragma unroll
        for (int ni = 0; ni < 4; ++ni) {
            int n = n0 + warp_n + ni * 8 + 2 * tig;
            float bi0 = __ldg(bias + n);
            float bi1 = __ldg(bias + n + 1);
            int which = n >> 10;
            int cidx  = n & 1023;
            int h     = cidx >> 6;
            int dd    = cidx & 63;
            float* dst = (which == 0) ? g_q : ((which == 1) ? g_k : g_v);
            dst += ((size_t)((b << 4) + h) * 2048) * 64;
            float2 v0 = make_float2(acc[mi][ni][0] + bi0, acc[mi][ni][1] + bi1);
            float2 v1 = make_float2(acc[mi][ni][2] + bi0, acc[mi][ni][3] + bi1);
            *(float2*)(dst + (size_t)t * 64 + dd)       = v0;
            *(float2*)(dst + (size_t)(t + 8) * 64 + dd) = v1;
        }
    }
}

// ---------------------------------------------------------------------------
// Kernel 2: flash attention via mma.sync tf32.
// BM=128 queries/CTA (8 warps x 16 rows), BN=64 keys/iter, d=64.
// Q fragments live in registers; P staged through warp-private SMEM reusing
// the Q staging buffer. K pitch 68, V pitch 72: conflict-free frag loads.
// ---------------------------------------------------------------------------
#define QP 68
#define KP 68
#define VP 72
#define PSTG (128 * QP)              // 8704 floats (Q stage, then 8x warp P)
#define KSZ  (64 * KP)               // 4352
#define VSZ  (64 * VP)               // 4608
#define FLASH_SMEM_BYTES ((PSTG + 2 * KSZ + 2 * VSZ + 64) * 4)

__device__ __forceinline__ void kv_stage(float* K, float* V, int base, int kb,
                                         int tid, uint32_t sK, uint32_t sV)
{
#pragma unroll
    for (int it = 0; it < 4; ++it) {
        int f   = it * 256 + tid;
        int row = f >> 4;
        int seg = f & 15;
        cp16(sK + (row * KP + seg * 4) * 4, g_k + (size_t)base + (kb + row) * 64 + seg * 4);
        cp16(sV + (row * VP + seg * 4) * 4, g_v + (size_t)base + (kb + row) * 64 + seg * 4);
    }
}

__global__ __launch_bounds__(256)
void flash_attn_mma(const int* __restrict__ mask, float* __restrict__ out)
{
    extern __shared__ float sm[];
    float* Pst = sm;                      // Q stage -> per-warp P
    float* K0  = sm + PSTG;
    float* K1  = K0 + KSZ;
    float* V0  = K1 + KSZ;
    float* V1  = V0 + VSZ;
    int*   Ms  = (int*)(V1 + VSZ);

    const int tid  = threadIdx.x;
    const int wid  = tid >> 5;
    const int lane = tid & 31;
    const int gid  = lane >> 2;
    const int tig  = lane & 3;
    const int bh   = blockIdx.y;
    const int b    = bh >> 4;
    const int h    = bh & 15;
    const int q0   = blockIdx.x * 128;
    const int base = bh * (T_ * D_);

    const uint32_t sK0 = smem_u32(K0), sK1 = smem_u32(K1);
    const uint32_t sV0 = smem_u32(V0), sV1 = smem_u32(V1);

    // Stage Q (scaled by 1/8) into Pst, then frag to registers.
#pragma unroll
    for (int it = 0; it < 8; ++it) {
        int f   = it * 256 + tid;
        int row = f >> 4;
        int seg = f & 15;
        float4 v = *(const float4*)(g_q + (size_t)base + (q0 + row) * 64 + seg * 4);
        v.x *= 0.125f; v.y *= 0.125f; v.z *= 0.125f; v.w *= 0.125f;
        *(float4*)&Pst[row * QP + seg * 4] = v;
    }
    __syncthreads();

    uint32_t qa[8][4];
    {
        int r0 = wid * 16 + gid;
#pragma unroll
        for (int s = 0; s < 8; ++s) {
            int kc = s * 8 + tig;
            qa[s][0] = cvt_tf32(Pst[r0 * QP + kc]);
            qa[s][1] = cvt_tf32(Pst[(r0 + 8) * QP + kc]);
            qa[s][2] = cvt_tf32(Pst[r0 * QP + kc + 4]);
            qa[s][3] = cvt_tf32(Pst[(r0 + 8) * QP + kc + 4]);
        }
    }
    float* Pw = Pst + wid * 16 * QP;       // this warp's 16 rows (just fragged)

    float o[8][4];
#pragma unroll
    for (int j = 0; j < 8; ++j)
#pragma unroll
        for (int r = 0; r < 4; ++r) o[j][r] = 0.f;
    float m0r = -1e30f, m1r = -1e30f, l0r = 0.f, l1r = 0.f;

    kv_stage(K0, V0, base, 0, tid, sK0, sV0);
    CP_COMMIT();

    for (int it = 0; it < 32; ++it) {
        const int kb = it * 64;
        if (it < 31) {
            kv_stage((it & 1) ? K0 : K1, (it & 1) ? V0 : V1, base, kb + 64, tid,
                     (it & 1) ? sK0 : sK1, (it & 1) ? sV0 : sV1);
            CP_COMMIT();
            CP_WAIT1();
        } else {
            CP_WAIT0();
        }
        if (tid < 64) Ms[tid] = mask[b * T_ + kb + tid];
        __syncthreads();

        const float* Ks = (it & 1) ? K1 : K0;
        const float* Vs = (it & 1) ? V1 : V0;

        // S = Q . K^T
        float s[8][4];
#pragma unroll
        for (int j = 0; j < 8; ++j)
#pragma unroll
            for (int r = 0; r < 4; ++r) s[j][r] = 0.f;
#pragma unroll
        for (int st = 0; st < 8; ++st) {
            int kc = st * 8 + tig;
#pragma unroll
            for (int j = 0; j < 8; ++j) {
                int key = j * 8 + gid;
                uint32_t b0 = cvt_tf32(Ks[key * KP + kc]);
                uint32_t b1 = cvt_tf32(Ks[key * KP + kc + 4]);
                mma_tf32(s[j], qa[st], b0, b1);
            }
        }

        // Mask
#pragma unroll
        for (int j = 0; j < 8; ++j) {
            int ca = j * 8 + 2 * tig;
            if (Ms[ca]     == 0) { s[j][0] = -INFINITY; s[j][2] = -INFINITY; }
            if (Ms[ca + 1] == 0) { s[j][1] = -INFINITY; s[j][3] = -INFINITY; }
        }

        // Online softmax (rows gid and gid+8; reduce across 4 tig lanes)
        float rm0 = -INFINITY, rm1 = -INFINITY;
#pragma unroll
        for (int j = 0; j < 8; ++j) {
            rm0 = fmaxf(rm0, fmaxf(s[j][0], s[j][1]));
            rm1 = fmaxf(rm1, fmaxf(s[j][2], s[j][3]));
        }
        rm0 = fmaxf(rm0, __shfl_xor_sync(0xffffffffu, rm0, 1));
        rm0 = fmaxf(rm0, __shfl_xor_sync(0xffffffffu, rm0, 2));
        rm1 = fmaxf(rm1, __shfl_xor_sync(0xffffffffu, rm1, 1));
        rm1 = fmaxf(rm1, __shfl_xor_sync(0xffffffffu, rm1, 2));

        float mn0 = fmaxf(m0r, rm0), mn1 = fmaxf(m1r, rm1);
        float sc0 = __expf(m0r - mn0), sc1 = __expf(m1r - mn1);
        m0r = mn0; m1r = mn1;

        float rs0 = 0.f, rs1 = 0.f;
#pragma unroll
        for (int j = 0; j < 8; ++j) {
            s[j][0] = __expf(s[j][0] - mn0); rs0 += s[j][0];
            s[j][1] = __expf(s[j][1] - mn0); rs0 += s[j][1];
            s[j][2] = __expf(s[j][2] - mn1); rs1 += s[j][2];
            s[j][3] = __expf(s[j][3] - mn1); rs1 += s[j][3];
        }
        rs0 += __shfl_xor_sync(0xffffffffu, rs0, 1);
        rs0 += __shfl_xor_sync(0xffffffffu, rs0, 2);
        rs1 += __shfl_xor_sync(0xffffffffu, rs1, 1);
        rs1 += __shfl_xor_sync(0xffffffffu, rs1, 2);
        l0r = l0r * sc0 + rs0;
        l1r = l1r * sc1 + rs1;

#pragma unroll
        for (int j = 0; j < 8; ++j) {
            o[j][0] *= sc0; o[j][1] *= sc0;
            o[j][2] *= sc1; o[j][3] *= sc1;
        }

        // P to warp-private smem
#pragma unroll
        for (int j = 0; j < 8; ++j) {
            int col = j * 8 + 2 * tig;
            *(float2*)&Pw[gid * QP + col]       = make_float2(s[j][0], s[j][1]);
            *(float2*)&Pw[(gid + 8) * QP + col] = make_float2(s[j][2], s[j][3]);
        }
        __syncwarp();

        // O += P . V
#pragma unroll
        for (int st = 0; st < 8; ++st) {
            int kc = st * 8 + tig;
            uint32_t pa[4];
            pa[0] = cvt_tf32(Pw[gid * QP + kc]);
            pa[1] = cvt_tf32(Pw[(gid + 8) * QP + kc]);
            pa[2] = cvt_tf32(Pw[gid * QP + kc + 4]);
            pa[3] = cvt_tf32(Pw[(gid + 8) * QP + kc + 4]);
#pragma unroll
            for (int j = 0; j < 8; ++j) {
                int dc = j * 8 + gid;
                uint32_t b0 = cvt_tf32(Vs[kc * VP + dc]);
                uint32_t b1 = cvt_tf32(Vs[(kc + 4) * VP + dc]);
                mma_tf32(o[j], pa, b0, b1);
            }
        }
        __syncthreads();
    }

    // Output: reference's flat (B,H,T,d)->(B,T,C) reshape
    float inv0 = 1.f / l0r, inv1 = 1.f / l1r;
#pragma unroll
    for (int row = 0; row < 2; ++row) {
        int q     = q0 + wid * 16 + gid + row * 8;
        int t_out = h * 128 + (q >> 4);
        int cbase = (q & 15) << 6;
        float inv = row ? inv1 : inv0;
#pragma unroll
        for (int j = 0; j < 8; ++j) {
            int dd = j * 8 + 2 * tig;
            float2 v = make_float2(o[j][2 * row] * inv, o[j][2 * row + 1] * inv);
            *(float2*)(out + (size_t)(b * T_ + t_out) * C_ + cbase + dd) = v;
        }
    }
}

// ---------------------------------------------------------------------------
// Launch
// ---------------------------------------------------------------------------
extern "C" void kernel_launch(void* const* d_in, const int* in_sizes, int n_in,
                              void* d_out, int out_size)
{
    const float* x    = (const float*)d_in[0];
    const int*   mask = (const int*)d_in[1];
    const float* W    = (const float*)d_in[2];
    const float* bq   = (const float*)d_in[3];
    float*       out  = (float*)d_out;

    cudaFuncSetAttribute(qkv_gemm_mma,
                         cudaFuncAttributeMaxDynamicSharedMemorySize, GEMM_SMEM_BYTES);
    cudaFuncSetAttribute(flash_attn_mma,
                         cudaFuncAttributeMaxDynamicSharedMemorySize, FLASH_SMEM_BYTES);

    dim3 g1(N_TOT / 128, M_TOT / 128);   // 24 x 128
    qkv_gemm_mma<<<g1, 256, GEMM_SMEM_BYTES>>>(x, W, bq);

    dim3 g2(T_ / 128, B_ * H_);          // 16 x 128
    flash_attn_mma<<<g2, 256, FLASH_SMEM_BYTES>>>(mask, out);
}

// round 8
// speedup vs baseline: 4.0337x; 1.2296x over previous
#include <cuda_runtime.h>
#include <math.h>
#include <stdint.h>

// Problem constants (B=8, T=2048, C=1024, H=16, d=64)
#define B_  8
#define T_  2048
#define C_  1024
#define H_  16
#define D_  64
#define M_TOT 16384
#define N_TOT 3072
#define K_TOT 1024

// q/k/v scratch in (B,H,T,d) layout, values pre-rounded to tf32 bit patterns.
__device__ float g_q[B_ * H_ * T_ * D_];
__device__ float g_k[B_ * H_ * T_ * D_];
__device__ float g_v[B_ * H_ * T_ * D_];
// tf32-pre-rounded copies of X and W (so the GEMM mainloop has zero cvts).
__device__ float g_xr[(size_t)M_TOT * K_TOT];
__device__ float g_wr[(size_t)K_TOT * N_TOT];

// ---------------------------------------------------------------------------
// Helpers
// ---------------------------------------------------------------------------
__device__ __forceinline__ uint32_t cvt_tf32(float x) {
    uint32_t r;
    asm("cvt.rna.tf32.f32 %0, %1;" : "=r"(r) : "f"(x));
    return r;
}

// D += A(16x8) * B(8x8), tf32 inputs, f32 accumulate.
__device__ __forceinline__ void mma_tf32(float* d, const uint32_t* a,
                                         uint32_t b0, uint32_t b1) {
    asm volatile(
        "mma.sync.aligned.m16n8k8.row.col.f32.tf32.tf32.f32 "
        "{%0,%1,%2,%3}, {%4,%5,%6,%7}, {%8,%9}, {%0,%1,%2,%3};"
        : "+f"(d[0]), "+f"(d[1]), "+f"(d[2]), "+f"(d[3])
        : "r"(a[0]), "r"(a[1]), "r"(a[2]), "r"(a[3]), "r"(b0), "r"(b1));
}

__device__ __forceinline__ uint32_t smem_u32(const void* p) {
    uint32_t a;
    asm("{ .reg .u64 t; cvta.to.shared.u64 t, %1; cvt.u32.u64 %0, t; }"
        : "=r"(a) : "l"(p));
    return a;
}
__device__ __forceinline__ void cp16(uint32_t s, const void* g) {
    asm volatile("cp.async.cg.shared.global [%0], [%1], 16;" :: "r"(s), "l"(g));
}
#define CP_COMMIT() asm volatile("cp.async.commit_group;" ::: "memory")
#define CP_WAIT0()  asm volatile("cp.async.wait_group 0;" ::: "memory")
#define CP_WAIT1()  asm volatile("cp.async.wait_group 1;" ::: "memory")

// ---------------------------------------------------------------------------
// Kernel 0: elementwise tf32 pre-round into device globals (no host-side
// symbol lookup, no static state in kernel_launch).
// ---------------------------------------------------------------------------
__global__ __launch_bounds__(256)
void round_x_pass(const float4* __restrict__ in)
{
    float4* out = (float4*)g_xr;
    int n4 = (M_TOT * K_TOT) / 4;
    int i = blockIdx.x * blockDim.x + threadIdx.x;
    int stride = gridDim.x * blockDim.x;
    for (; i < n4; i += stride) {
        float4 v = in[i];
        v.x = __uint_as_float(cvt_tf32(v.x));
        v.y = __uint_as_float(cvt_tf32(v.y));
        v.z = __uint_as_float(cvt_tf32(v.z));
        v.w = __uint_as_float(cvt_tf32(v.w));
        out[i] = v;
    }
}

__global__ __launch_bounds__(256)
void round_w_pass(const float4* __restrict__ in)
{
    float4* out = (float4*)g_wr;
    int n4 = (K_TOT * N_TOT) / 4;
    int i = blockIdx.x * blockDim.x + threadIdx.x;
    int stride = gridDim.x * blockDim.x;
    for (; i < n4; i += stride) {
        float4 v = in[i];
        v.x = __uint_as_float(cvt_tf32(v.x));
        v.y = __uint_as_float(cvt_tf32(v.y));
        v.z = __uint_as_float(cvt_tf32(v.z));
        v.w = __uint_as_float(cvt_tf32(v.w));
        out[i] = v;
    }
}

// ---------------------------------------------------------------------------
// Kernel 1: QKV GEMM via mma.sync tf32 on pre-rounded inputs (no cvts).
// CTA 128x128, BK=32, 8 warps as 2(m) x 4(n) -> warp tile 64x32.
// Pitches: A 36 (=4 mod 32), B 136 (=8 mod 32) -> conflict-free frag loads.
// ---------------------------------------------------------------------------
#define APITCH 36
#define BPITCH 136
#define ASZ (128 * APITCH)
#define BSZ (32 * BPITCH)
#define GEMM_SMEM_BYTES ((2 * ASZ + 2 * BSZ) * 4)

__device__ __forceinline__ void gemm_stage(const float* __restrict__ X,
                                           const float* __restrict__ W,
                                           int m0, int n0, int k0, int tid,
                                           uint32_t sA, uint32_t sB)
{
#pragma unroll
    for (int it = 0; it < 4; ++it) {          // A: 128 rows x 32 floats
        int f   = it * 256 + tid;
        int row = f >> 3;
        int seg = f & 7;
        cp16(sA + (row * APITCH + seg * 4) * 4,
             X + (size_t)(m0 + row) * K_TOT + k0 + seg * 4);
    }
#pragma unroll
    for (int it = 0; it < 4; ++it) {          // B: 32 rows x 128 floats
        int f   = it * 256 + tid;
        int row = f >> 5;
        int seg = f & 31;
        cp16(sB + (row * BPITCH + seg * 4) * 4,
             W + (size_t)(k0 + row) * N_TOT + n0 + seg * 4);
    }
}

__global__ __launch_bounds__(256)
void qkv_gemm_mma(const float* __restrict__ bias)
{
    extern __shared__ float sm[];
    float* A0 = sm;
    float* A1 = sm + ASZ;
    float* B0 = sm + 2 * ASZ;
    float* B1 = B0 + BSZ;

    const int tid  = threadIdx.x;
    const int wid  = tid >> 5;
    const int lane = tid & 31;
    const int gid  = lane >> 2;
    const int tig  = lane & 3;
    const int n0   = blockIdx.x * 128;
    const int m0   = blockIdx.y * 128;
    const int warp_m = (wid >> 2) * 64;
    const int warp_n = (wid & 3) * 32;

    const uint32_t sA0 = smem_u32(A0), sA1 = smem_u32(A1);
    const uint32_t sB0 = smem_u32(B0), sB1 = smem_u32(B1);
    const float* X = g_xr;
    const float* W = g_wr;

    float acc[4][4][4];
#pragma unroll
    for (int mi = 0; mi < 4; ++mi)
#pragma unroll
        for (int ni = 0; ni < 4; ++ni)
#pragma unroll
            for (int r = 0; r < 4; ++r) acc[mi][ni][r] = 0.f;

    gemm_stage(X, W, m0, n0, 0, tid, sA0, sB0);
    CP_COMMIT();

    for (int it = 0; it < 32; ++it) {
        if (it < 31) {
            gemm_stage(X, W, m0, n0, (it + 1) * 32, tid,
                       (it & 1) ? sA0 : sA1, (it & 1) ? sB0 : sB1);
            CP_COMMIT();
            CP_WAIT1();
        } else {
            CP_WAIT0();
        }
        __syncthreads();

        const uint32_t* A = (const uint32_t*)((it & 1) ? A1 : A0);
        const uint32_t* B = (const uint32_t*)((it & 1) ? B1 : B0);

#pragma unroll
        for (int s = 0; s < 4; ++s) {         // 4 ksteps of k=8
            uint32_t af[4][4];
#pragma unroll
            for (int mi = 0; mi < 4; ++mi) {
                int r0 = warp_m + mi * 16 + gid;
                int kc = s * 8 + tig;
                af[mi][0] = A[r0 * APITCH + kc];
                af[mi][1] = A[(r0 + 8) * APITCH + kc];
                af[mi][2] = A[r0 * APITCH + kc + 4];
                af[mi][3] = A[(r0 + 8) * APITCH + kc + 4];
            }
            uint32_t bf[4][2];
#pragma unroll
            for (int ni = 0; ni < 4; ++ni) {
                int nc = warp_n + ni * 8 + gid;
                int kc = s * 8 + tig;
                bf[ni][0] = B[kc * BPITCH + nc];
                bf[ni][1] = B[(kc + 4) * BPITCH + nc];
            }
#pragma unroll
            for (int mi = 0; mi < 4; ++mi)
#pragma unroll
                for (int ni = 0; ni < 4; ++ni)
                    mma_tf32(acc[mi][ni], af[mi], bf[ni][0], bf[ni][1]);
        }
        __syncthreads();
    }

    // Epilogue: add bias (fp32), round to tf32 bits, scatter into q/k/v.
#pragma unroll
    for (int mi = 0; mi < 4; ++mi) {
        int m = m0 + warp_m + mi * 16 + gid;
        int b = m >> 11;
        int t = m & 2047;
#pragma unroll
        for (int ni = 0; ni < 4; ++ni) {
            int n = n0 + warp_n + ni * 8 + 2 * tig;
            float bi0 = __ldg(bias + n);
            float bi1 = __ldg(bias + n + 1);
            int which = n >> 10;
            int cidx  = n & 1023;
            int h     = cidx >> 6;
            int dd    = cidx & 63;
            float* dst = (which == 0) ? g_q : ((which == 1) ? g_k : g_v);
            dst += ((size_t)((b << 4) + h) * 2048) * 64;
            float2 v0 = make_float2(__uint_as_float(cvt_tf32(acc[mi][ni][0] + bi0)),
                                    __uint_as_float(cvt_tf32(acc[mi][ni][1] + bi1)));
            float2 v1 = make_float2(__uint_as_float(cvt_tf32(acc[mi][ni][2] + bi0)),
                                    __uint_as_float(cvt_tf32(acc[mi][ni][3] + bi1)));
            *(float2*)(dst + (size_t)t * 64 + dd)       = v0;
            *(float2*)(dst + (size_t)(t + 8) * 64 + dd) = v1;
        }
    }
}

// ---------------------------------------------------------------------------
// Kernel 2: flash attention via mma.sync tf32 on pre-rounded q/k/v.
// BM=128 queries/CTA (8 warps x 16 rows), BN=64 keys/iter, d=64.
// K/V/Q fragments are raw bit loads (no cvt). Only P converts post-exp.
// ---------------------------------------------------------------------------
#define QP 68
#define KP 68
#define VP 72
#define PSTG (128 * QP)
#define KSZ  (64 * KP)
#define VSZ  (64 * VP)
#define FLASH_SMEM_BYTES ((PSTG + 2 * KSZ + 2 * VSZ + 64) * 4)

__device__ __forceinline__ void kv_stage(int base, int kb, int tid,
                                         uint32_t sK, uint32_t sV)
{
#pragma unroll
    for (int it = 0; it < 4; ++it) {
        int f   = it * 256 + tid;
        int row = f >> 4;
        int seg = f & 15;
        cp16(sK + (row * KP + seg * 4) * 4, g_k + (size_t)base + (kb + row) * 64 + seg * 4);
        cp16(sV + (row * VP + seg * 4) * 4, g_v + (size_t)base + (kb + row) * 64 + seg * 4);
    }
}

__global__ __launch_bounds__(256)
void flash_attn_mma(const int* __restrict__ mask, float* __restrict__ out)
{
    extern __shared__ float sm[];
    float* Pst = sm;                      // Q stage -> per-warp P
    float* K0  = sm + PSTG;
    float* K1  = K0 + KSZ;
    float* V0  = K1 + KSZ;
    float* V1  = V0 + VSZ;
    int*   Ms  = (int*)(V1 + VSZ);

    const int tid  = threadIdx.x;
    const int wid  = tid >> 5;
    const int lane = tid & 31;
    const int gid  = lane >> 2;
    const int tig  = lane & 3;
    const int bh   = blockIdx.y;
    const int b    = bh >> 4;
    const int h    = bh & 15;
    const int q0   = blockIdx.x * 128;
    const int base = bh * (T_ * D_);

    const uint32_t sK0 = smem_u32(K0), sK1 = smem_u32(K1);
    const uint32_t sV0 = smem_u32(V0), sV1 = smem_u32(V1);

    // Stage Q (x 0.125, exact on tf32 values) into Pst, frag to registers.
#pragma unroll
    for (int it = 0; it < 8; ++it) {
        int f   = it * 256 + tid;
        int row = f >> 4;
        int seg = f & 15;
        float4 v = *(const float4*)(g_q + (size_t)base + (q0 + row) * 64 + seg * 4);
        v.x *= 0.125f; v.y *= 0.125f; v.z *= 0.125f; v.w *= 0.125f;
        *(float4*)&Pst[row * QP + seg * 4] = v;
    }
    __syncthreads();

    uint32_t qa[8][4];
    {
        const uint32_t* Pu = (const uint32_t*)Pst;
        int r0 = wid * 16 + gid;
#pragma unroll
        for (int s = 0; s < 8; ++s) {
            int kc = s * 8 + tig;
            qa[s][0] = Pu[r0 * QP + kc];
            qa[s][1] = Pu[(r0 + 8) * QP + kc];
            qa[s][2] = Pu[r0 * QP + kc + 4];
            qa[s][3] = Pu[(r0 + 8) * QP + kc + 4];
        }
    }
    float* Pw = Pst + wid * 16 * QP;       // this warp's 16 rows (just fragged)

    float o[8][4];
#pragma unroll
    for (int j = 0; j < 8; ++j)
#pragma unroll
        for (int r = 0; r < 4; ++r) o[j][r] = 0.f;
    float m0r = -1e30f, m1r = -1e30f, l0r = 0.f, l1r = 0.f;

    kv_stage(base, 0, tid, sK0, sV0);
    CP_COMMIT();

    for (int it = 0; it < 32; ++it) {
        const int kb = it * 64;
        if (it < 31) {
            kv_stage(base, kb + 64, tid,
                     (it & 1) ? sK0 : sK1, (it & 1) ? sV0 : sV1);
            CP_COMMIT();
            CP_WAIT1();
        } else {
            CP_WAIT0();
        }
        if (tid < 64) Ms[tid] = mask[b * T_ + kb + tid];
        __syncthreads();

        const uint32_t* Ks = (const uint32_t*)((it & 1) ? K1 : K0);
        const uint32_t* Vs = (const uint32_t*)((it & 1) ? V1 : V0);

        // S = Q . K^T (raw tf32 bit loads)
        float s[8][4];
#pragma unroll
        for (int j = 0; j < 8; ++j)
#pragma unroll
            for (int r = 0; r < 4; ++r) s[j][r] = 0.f;
#pragma unroll
        for (int st = 0; st < 8; ++st) {
            int kc = st * 8 + tig;
#pragma unroll
            for (int j = 0; j < 8; ++j) {
                int key = j * 8 + gid;
                mma_tf32(s[j], qa[st], Ks[key * KP + kc], Ks[key * KP + kc + 4]);
            }
        }

        // Mask
#pragma unroll
        for (int j = 0; j < 8; ++j) {
            int ca = j * 8 + 2 * tig;
            if (Ms[ca]     == 0) { s[j][0] = -INFINITY; s[j][2] = -INFINITY; }
            if (Ms[ca + 1] == 0) { s[j][1] = -INFINITY; s[j][3] = -INFINITY; }
        }

        // Online softmax (rows gid and gid+8; reduce across 4 tig lanes)
        float rm0 = -INFINITY, rm1 = -INFINITY;
#pragma unroll
        for (int j = 0; j < 8; ++j) {
            rm0 = fmaxf(rm0, fmaxf(s[j][0], s[j][1]));
            rm1 = fmaxf(rm1, fmaxf(s[j][2], s[j][3]));
        }
        rm0 = fmaxf(rm0, __shfl_xor_sync(0xffffffffu, rm0, 1));
        rm0 = fmaxf(rm0, __shfl_xor_sync(0xffffffffu, rm0, 2));
        rm1 = fmaxf(rm1, __shfl_xor_sync(0xffffffffu, rm1, 1));
        rm1 = fmaxf(rm1, __shfl_xor_sync(0xffffffffu, rm1, 2));

        float mn0 = fmaxf(m0r, rm0), mn1 = fmaxf(m1r, rm1);
        float sc0 = __expf(m0r - mn0), sc1 = __expf(m1r - mn1);
        m0r = mn0; m1r = mn1;

        float rs0 = 0.f, rs1 = 0.f;
#pragma unroll
        for (int j = 0; j < 8; ++j) {
            s[j][0] = __expf(s[j][0] - mn0); rs0 += s[j][0];
            s[j][1] = __expf(s[j][1] - mn0); rs0 += s[j][1];
            s[j][2] = __expf(s[j][2] - mn1); rs1 += s[j][2];
            s[j][3] = __expf(s[j][3] - mn1); rs1 += s[j][3];
        }
        rs0 += __shfl_xor_sync(0xffffffffu, rs0, 1);
        rs0 += __shfl_xor_sync(0xffffffffu, rs0, 2);
        rs1 += __shfl_xor_sync(0xffffffffu, rs1, 1);
        rs1 += __shfl_xor_sync(0xffffffffu, rs1, 2);
        l0r = l0r * sc0 + rs0;
        l1r = l1r * sc1 + rs1;

#pragma unroll
        for (int j = 0; j < 8; ++j) {
            o[j][0] *= sc0; o[j][1] *= sc0;
            o[j][2] *= sc1; o[j][3] *= sc1;
        }

        // P to warp-private smem, pre-rounded to tf32 bits at store time
#pragma unroll
        for (int j = 0; j < 8; ++j) {
            int col = j * 8 + 2 * tig;
            float2 p0 = make_float2(__uint_as_float(cvt_tf32(s[j][0])),
                                    __uint_as_float(cvt_tf32(s[j][1])));
            float2 p1 = make_float2(__uint_as_float(cvt_tf32(s[j][2])),
                                    __uint_as_float(cvt_tf32(s[j][3])));
            *(float2*)&Pw[gid * QP + col]       = p0;
            *(float2*)&Pw[(gid + 8) * QP + col] = p1;
        }
        __syncwarp();

        // O += P . V (raw bit loads)
        const uint32_t* Pwu = (const uint32_t*)Pw;
#pragma unroll
        for (int st = 0; st < 8; ++st) {
            int kc = st * 8 + tig;
            uint32_t pa[4];
            pa[0] = Pwu[gid * QP + kc];
            pa[1] = Pwu[(gid + 8) * QP + kc];
            pa[2] = Pwu[gid * QP + kc + 4];
            pa[3] = Pwu[(gid + 8) * QP + kc + 4];
#pragma unroll
            for (int j = 0; j < 8; ++j) {
                int dc = j * 8 + gid;
                mma_tf32(o[j], pa, Vs[kc * VP + dc], Vs[(kc + 4) * VP + dc]);
            }
        }
        __syncthreads();
    }

    // Output: reference's flat (B,H,T,d)->(B,T,C) reshape
    float inv0 = 1.f / l0r, inv1 = 1.f / l1r;
#pragma unroll
    for (int row = 0; row < 2; ++row) {
        int q     = q0 + wid * 16 + gid + row * 8;
        int t_out = h * 128 + (q >> 4);
        int cbase = (q & 15) << 6;
        float inv = row ? inv1 : inv0;
#pragma unroll
        for (int j = 0; j < 8; ++j) {
            int dd = j * 8 + 2 * tig;
            float2 v = make_float2(o[j][2 * row] * inv, o[j][2 * row + 1] * inv);
            *(float2*)(out + (size_t)(b * T_ + t_out) * C_ + cbase + dd) = v;
        }
    }
}

// ---------------------------------------------------------------------------
// Launch (stateless: no static guards, no symbol lookups)
// ---------------------------------------------------------------------------
extern "C" void kernel_launch(void* const* d_in, const int* in_sizes, int n_in,
                              void* d_out, int out_size)
{
    const float* x    = (const float*)d_in[0];
    const int*   mask = (const int*)d_in[1];
    const float* W    = (const float*)d_in[2];
    const float* bq   = (const float*)d_in[3];
    float*       out  = (float*)d_out;

    cudaFuncSetAttribute(qkv_gemm_mma,
                         cudaFuncAttributeMaxDynamicSharedMemorySize, GEMM_SMEM_BYTES);
    cudaFuncSetAttribute(flash_attn_mma,
                         cudaFuncAttributeMaxDynamicSharedMemorySize, FLASH_SMEM_BYTES);

    // Pre-round X and W to tf32 (removes all cvts from the GEMM mainloop).
    round_x_pass<<<2048, 256>>>((const float4*)x);
    round_w_pass<<<1024, 256>>>((const float4*)W);

    dim3 g1(N_TOT / 128, M_TOT / 128);   // 24 x 128
    qkv_gemm_mma<<<g1, 256, GEMM_SMEM_BYTES>>>(bq);

    dim3 g2(T_ / 128, B_ * H_);          // 16 x 128
    flash_attn_mma<<<g2, 256, FLASH_SMEM_BYTES>>>(mask, out);
}

// round 9
// speedup vs baseline: 4.1028x; 1.0171x over previous
#include <cuda_runtime.h>
#include <math.h>
#include <stdint.h>

// Problem constants (B=8, T=2048, C=1024, H=16, d=64)
#define B_  8
#define T_  2048
#define C_  1024
#define H_  16
#define D_  64
#define M_TOT 16384
#define N_TOT 3072
#define K_TOT 1024

// q/k/v scratch in (B,H,T,d) layout, values pre-rounded to tf32 bit patterns.
__device__ float g_q[B_ * H_ * T_ * D_];
__device__ float g_k[B_ * H_ * T_ * D_];
__device__ float g_v[B_ * H_ * T_ * D_];
// tf32-pre-rounded copies of X and W (so the GEMM mainloop has zero cvts).
__device__ float g_xr[(size_t)M_TOT * K_TOT];
__device__ float g_wr[(size_t)K_TOT * N_TOT];

// ---------------------------------------------------------------------------
// Helpers
// ---------------------------------------------------------------------------
__device__ __forceinline__ uint32_t cvt_tf32(float x) {
    uint32_t r;
    asm("cvt.rna.tf32.f32 %0, %1;" : "=r"(r) : "f"(x));
    return r;
}

// D += A(16x8) * B(8x8), tf32 inputs, f32 accumulate.
__device__ __forceinline__ void mma_tf32(float* d, const uint32_t* a,
                                         uint32_t b0, uint32_t b1) {
    asm volatile(
        "mma.sync.aligned.m16n8k8.row.col.f32.tf32.tf32.f32 "
        "{%0,%1,%2,%3}, {%4,%5,%6,%7}, {%8,%9}, {%0,%1,%2,%3};"
        : "+f"(d[0]), "+f"(d[1]), "+f"(d[2]), "+f"(d[3])
        : "r"(a[0]), "r"(a[1]), "r"(a[2]), "r"(a[3]), "r"(b0), "r"(b1));
}

__device__ __forceinline__ uint32_t smem_u32(const void* p) {
    uint32_t a;
    asm("{ .reg .u64 t; cvta.to.shared.u64 t, %1; cvt.u32.u64 %0, t; }"
        : "=r"(a) : "l"(p));
    return a;
}
__device__ __forceinline__ void cp16(uint32_t s, const void* g) {
    asm volatile("cp.async.cg.shared.global [%0], [%1], 16;" :: "r"(s), "l"(g));
}
#define CP_COMMIT() asm volatile("cp.async.commit_group;" ::: "memory")
#define CP_WAIT0()  asm volatile("cp.async.wait_group 0;" ::: "memory")
#define CP_WAIT1()  asm volatile("cp.async.wait_group 1;" ::: "memory")

// ---------------------------------------------------------------------------
// Kernel 0: elementwise tf32 pre-round into device globals
// ---------------------------------------------------------------------------
__global__ __launch_bounds__(256)
void round_x_pass(const float4* __restrict__ in)
{
    float4* out = (float4*)g_xr;
    int n4 = (M_TOT * K_TOT) / 4;
    int i = blockIdx.x * blockDim.x + threadIdx.x;
    int stride = gridDim.x * blockDim.x;
    for (; i < n4; i += stride) {
        float4 v = in[i];
        v.x = __uint_as_float(cvt_tf32(v.x));
        v.y = __uint_as_float(cvt_tf32(v.y));
        v.z = __uint_as_float(cvt_tf32(v.z));
        v.w = __uint_as_float(cvt_tf32(v.w));
        out[i] = v;
    }
}

__global__ __launch_bounds__(256)
void round_w_pass(const float4* __restrict__ in)
{
    float4* out = (float4*)g_wr;
    int n4 = (K_TOT * N_TOT) / 4;
    int i = blockIdx.x * blockDim.x + threadIdx.x;
    int stride = gridDim.x * blockDim.x;
    for (; i < n4; i += stride) {
        float4 v = in[i];
        v.x = __uint_as_float(cvt_tf32(v.x));
        v.y = __uint_as_float(cvt_tf32(v.y));
        v.z = __uint_as_float(cvt_tf32(v.z));
        v.w = __uint_as_float(cvt_tf32(v.w));
        out[i] = v;
    }
}

// ---------------------------------------------------------------------------
// Kernel 1: QKV GEMM via mma.sync tf32 on pre-rounded inputs (unchanged).
// ---------------------------------------------------------------------------
#define APITCH 36
#define BPITCH 136
#define ASZ (128 * APITCH)
#define BSZ (32 * BPITCH)
#define GEMM_SMEM_BYTES ((2 * ASZ + 2 * BSZ) * 4)

__device__ __forceinline__ void gemm_stage(const float* __restrict__ X,
                                           const float* __restrict__ W,
                                           int m0, int n0, int k0, int tid,
                                           uint32_t sA, uint32_t sB)
{
#pragma unroll
    for (int it = 0; it < 4; ++it) {          // A: 128 rows x 32 floats
        int f   = it * 256 + tid;
        int row = f >> 3;
        int seg = f & 7;
        cp16(sA + (row * APITCH + seg * 4) * 4,
             X + (size_t)(m0 + row) * K_TOT + k0 + seg * 4);
    }
#pragma unroll
    for (int it = 0; it < 4; ++it) {          // B: 32 rows x 128 floats
        int f   = it * 256 + tid;
        int row = f >> 5;
        int seg = f & 31;
        cp16(sB + (row * BPITCH + seg * 4) * 4,
             W + (size_t)(k0 + row) * N_TOT + n0 + seg * 4);
    }
}

__global__ __launch_bounds__(256)
void qkv_gemm_mma(const float* __restrict__ bias)
{
    extern __shared__ float sm[];
    float* A0 = sm;
    float* A1 = sm + ASZ;
    float* B0 = sm + 2 * ASZ;
    float* B1 = B0 + BSZ;

    const int tid  = threadIdx.x;
    const int wid  = tid >> 5;
    const int lane = tid & 31;
    const int gid  = lane >> 2;
    const int tig  = lane & 3;
    const int n0   = blockIdx.x * 128;
    const int m0   = blockIdx.y * 128;
    const int warp_m = (wid >> 2) * 64;
    const int warp_n = (wid & 3) * 32;

    const uint32_t sA0 = smem_u32(A0), sA1 = smem_u32(A1);
    const uint32_t sB0 = smem_u32(B0), sB1 = smem_u32(B1);
    const float* X = g_xr;
    const float* W = g_wr;

    float acc[4][4][4];
#pragma unroll
    for (int mi = 0; mi < 4; ++mi)
#pragma unroll
        for (int ni = 0; ni < 4; ++ni)
#pragma unroll
            for (int r = 0; r < 4; ++r) acc[mi][ni][r] = 0.f;

    gemm_stage(X, W, m0, n0, 0, tid, sA0, sB0);
    CP_COMMIT();

    for (int it = 0; it < 32; ++it) {
        if (it < 31) {
            gemm_stage(X, W, m0, n0, (it + 1) * 32, tid,
                       (it & 1) ? sA0 : sA1, (it & 1) ? sB0 : sB1);
            CP_COMMIT();
            CP_WAIT1();
        } else {
            CP_WAIT0();
        }
        __syncthreads();

        const uint32_t* A = (const uint32_t*)((it & 1) ? A1 : A0);
        const uint32_t* B = (const uint32_t*)((it & 1) ? B1 : B0);

#pragma unroll
        for (int s = 0; s < 4; ++s) {         // 4 ksteps of k=8
            uint32_t af[4][4];
#pragma unroll
            for (int mi = 0; mi < 4; ++mi) {
                int r0 = warp_m + mi * 16 + gid;
                int kc = s * 8 + tig;
                af[mi][0] = A[r0 * APITCH + kc];
                af[mi][1] = A[(r0 + 8) * APITCH + kc];
                af[mi][2] = A[r0 * APITCH + kc + 4];
                af[mi][3] = A[(r0 + 8) * APITCH + kc + 4];
            }
            uint32_t bf[4][2];
#pragma unroll
            for (int ni = 0; ni < 4; ++ni) {
                int nc = warp_n + ni * 8 + gid;
                int kc = s * 8 + tig;
                bf[ni][0] = B[kc * BPITCH + nc];
                bf[ni][1] = B[(kc + 4) * BPITCH + nc];
            }
#pragma unroll
            for (int mi = 0; mi < 4; ++mi)
#pragma unroll
                for (int ni = 0; ni < 4; ++ni)
                    mma_tf32(acc[mi][ni], af[mi], bf[ni][0], bf[ni][1]);
        }
        __syncthreads();
    }

    // Epilogue: add bias (fp32), round to tf32 bits, scatter into q/k/v.
#pragma unroll
    for (int mi = 0; mi < 4; ++mi) {
        int m = m0 + warp_m + mi * 16 + gid;
        int b = m >> 11;
        int t = m & 2047;
#pragma unroll
        for (int ni = 0; ni < 4; ++ni) {
            int n = n0 + warp_n + ni * 8 + 2 * tig;
            float bi0 = __ldg(bias + n);
            float bi1 = __ldg(bias + n + 1);
            int which = n >> 10;
            int cidx  = n & 1023;
            int h     = cidx >> 6;
            int dd    = cidx & 63;
            float* dst = (which == 0) ? g_q : ((which == 1) ? g_k : g_v);
            dst += ((size_t)((b << 4) + h) * 2048) * 64;
            float2 v0 = make_float2(__uint_as_float(cvt_tf32(acc[mi][ni][0] + bi0)),
                                    __uint_as_float(cvt_tf32(acc[mi][ni][1] + bi1)));
            float2 v1 = make_float2(__uint_as_float(cvt_tf32(acc[mi][ni][2] + bi0)),
                                    __uint_as_float(cvt_tf32(acc[mi][ni][3] + bi1)));
            *(float2*)(dst + (size_t)t * 64 + dd)       = v0;
            *(float2*)(dst + (size_t)(t + 8) * 64 + dd) = v1;
        }
    }
}

// ---------------------------------------------------------------------------
// Kernel 2: flash attention, 2 m16-tiles per warp (32 query rows).
// BM=256 queries/CTA (8 warps x 32 rows), BN=64 keys/iter, d=64.
// Each K/V fragment load now feeds TWO mmas -> LDS bytes per MMA halved
// (the R8 profile showed LDS bandwidth and tensor pipe saturating together).
// ---------------------------------------------------------------------------
#define QP 68
#define KP 68
#define VP 72
#define PSTG (256 * QP)
#define KSZ  (64 * KP)
#define VSZ  (64 * VP)
#define FLASH_SMEM_BYTES ((PSTG + 2 * KSZ + 2 * VSZ + 64) * 4)

__device__ __forceinline__ void kv_stage(int base, int kb, int tid,
                                         uint32_t sK, uint32_t sV)
{
#pragma unroll
    for (int it = 0; it < 4; ++it) {
        int f   = it * 256 + tid;
        int row = f >> 4;
        int seg = f & 15;
        cp16(sK + (row * KP + seg * 4) * 4, g_k + (size_t)base + (kb + row) * 64 + seg * 4);
        cp16(sV + (row * VP + seg * 4) * 4, g_v + (size_t)base + (kb + row) * 64 + seg * 4);
    }
}

__global__ __launch_bounds__(256, 1)
void flash_attn_mma(const int* __restrict__ mask, float* __restrict__ out)
{
    extern __shared__ float sm[];
    float* Pst = sm;                      // Q stage -> per-warp P (256 rows)
    float* K0  = sm + PSTG;
    float* K1  = K0 + KSZ;
    float* V0  = K1 + KSZ;
    float* V1  = V0 + VSZ;
    int*   Ms  = (int*)(V1 + VSZ);

    const int tid  = threadIdx.x;
    const int wid  = tid >> 5;
    const int lane = tid & 31;
    const int gid  = lane >> 2;
    const int tig  = lane & 3;
    const int bh   = blockIdx.y;
    const int b    = bh >> 4;
    const int h    = bh & 15;
    const int q0   = blockIdx.x * 256;
    const int base = bh * (T_ * D_);

    const uint32_t sK0 = smem_u32(K0), sK1 = smem_u32(K1);
    const uint32_t sV0 = smem_u32(V0), sV1 = smem_u32(V1);

    // Stage Q (x 0.125, exact on tf32 values): 256 rows x 64 cols.
#pragma unroll
    for (int it = 0; it < 16; ++it) {
        int f   = it * 256 + tid;
        int row = f >> 4;
        int seg = f & 15;
        float4 v = *(const float4*)(g_q + (size_t)base + (q0 + row) * 64 + seg * 4);
        v.x *= 0.125f; v.y *= 0.125f; v.z *= 0.125f; v.w *= 0.125f;
        *(float4*)&Pst[row * QP + seg * 4] = v;
    }
    __syncthreads();

    // Q fragments for BOTH m16 tiles of this warp (rows wid*32 + mt*16 + ...)
    uint32_t qa[2][8][4];
    {
        const uint32_t* Pu = (const uint32_t*)Pst;
#pragma unroll
        for (int mt = 0; mt < 2; ++mt) {
            int r0 = wid * 32 + mt * 16 + gid;
#pragma unroll
            for (int s = 0; s < 8; ++s) {
                int kc = s * 8 + tig;
                qa[mt][s][0] = Pu[r0 * QP + kc];
                qa[mt][s][1] = Pu[(r0 + 8) * QP + kc];
                qa[mt][s][2] = Pu[r0 * QP + kc + 4];
                qa[mt][s][3] = Pu[(r0 + 8) * QP + kc + 4];
            }
        }
    }
    float* Pw = Pst + wid * 32 * QP;       // this warp's 32 rows (just fragged)

    float o[2][8][4];
#pragma unroll
    for (int mt = 0; mt < 2; ++mt)
#pragma unroll
        for (int j = 0; j < 8; ++j)
#pragma unroll
            for (int r = 0; r < 4; ++r) o[mt][j][r] = 0.f;
    float mrow[2][2], lrow[2][2];
#pragma unroll
    for (int mt = 0; mt < 2; ++mt) {
        mrow[mt][0] = -1e30f; mrow[mt][1] = -1e30f;
        lrow[mt][0] = 0.f;    lrow[mt][1] = 0.f;
    }

    kv_stage(base, 0, tid, sK0, sV0);
    CP_COMMIT();

    for (int it = 0; it < 32; ++it) {
        const int kb = it * 64;
        if (it < 31) {
            kv_stage(base, kb + 64, tid,
                     (it & 1) ? sK0 : sK1, (it & 1) ? sV0 : sV1);
            CP_COMMIT();
            CP_WAIT1();
        } else {
            CP_WAIT0();
        }
        if (tid < 64) Ms[tid] = mask[b * T_ + kb + tid];
        __syncthreads();

        const uint32_t* Ks = (const uint32_t*)((it & 1) ? K1 : K0);
        const uint32_t* Vs = (const uint32_t*)((it & 1) ? V1 : V0);

        // S = Q . K^T — each K fragment feeds both m-tiles
        float s[2][8][4];
#pragma unroll
        for (int mt = 0; mt < 2; ++mt)
#pragma unroll
            for (int j = 0; j < 8; ++j)
#pragma unroll
                for (int r = 0; r < 4; ++r) s[mt][j][r] = 0.f;
#pragma unroll
        for (int st = 0; st < 8; ++st) {
            int kc = st * 8 + tig;
#pragma unroll
            for (int j = 0; j < 8; ++j) {
                int key = j * 8 + gid;
                uint32_t b0 = Ks[key * KP + kc];
                uint32_t b1 = Ks[key * KP + kc + 4];
                mma_tf32(s[0][j], qa[0][st], b0, b1);
                mma_tf32(s[1][j], qa[1][st], b0, b1);
            }
        }

        // Mask (same key columns for both tiles)
#pragma unroll
        for (int j = 0; j < 8; ++j) {
            int ca = j * 8 + 2 * tig;
            if (Ms[ca] == 0) {
                s[0][j][0] = -INFINITY; s[0][j][2] = -INFINITY;
                s[1][j][0] = -INFINITY; s[1][j][2] = -INFINITY;
            }
            if (Ms[ca + 1] == 0) {
                s[0][j][1] = -INFINITY; s[0][j][3] = -INFINITY;
                s[1][j][1] = -INFINITY; s[1][j][3] = -INFINITY;
            }
        }

        // Online softmax per tile (rows gid, gid+8 within each tile)
#pragma unroll
        for (int mt = 0; mt < 2; ++mt) {
            float rm0 = -INFINITY, rm1 = -INFINITY;
#pragma unroll
            for (int j = 0; j < 8; ++j) {
                rm0 = fmaxf(rm0, fmaxf(s[mt][j][0], s[mt][j][1]));
                rm1 = fmaxf(rm1, fmaxf(s[mt][j][2], s[mt][j][3]));
            }
            rm0 = fmaxf(rm0, __shfl_xor_sync(0xffffffffu, rm0, 1));
            rm0 = fmaxf(rm0, __shfl_xor_sync(0xffffffffu, rm0, 2));
            rm1 = fmaxf(rm1, __shfl_xor_sync(0xffffffffu, rm1, 1));
            rm1 = fmaxf(rm1, __shfl_xor_sync(0xffffffffu, rm1, 2));

            float mn0 = fmaxf(mrow[mt][0], rm0), mn1 = fmaxf(mrow[mt][1], rm1);
            float sc0 = __expf(mrow[mt][0] - mn0), sc1 = __expf(mrow[mt][1] - mn1);
            mrow[mt][0] = mn0; mrow[mt][1] = mn1;

            float rs0 = 0.f, rs1 = 0.f;
#pragma unroll
            for (int j = 0; j < 8; ++j) {
                s[mt][j][0] = __expf(s[mt][j][0] - mn0); rs0 += s[mt][j][0];
                s[mt][j][1] = __expf(s[mt][j][1] - mn0); rs0 += s[mt][j][1];
                s[mt][j][2] = __expf(s[mt][j][2] - mn1); rs1 += s[mt][j][2];
                s[mt][j][3] = __expf(s[mt][j][3] - mn1); rs1 += s[mt][j][3];
            }
            rs0 += __shfl_xor_sync(0xffffffffu, rs0, 1);
            rs0 += __shfl_xor_sync(0xffffffffu, rs0, 2);
            rs1 += __shfl_xor_sync(0xffffffffu, rs1, 1);
            rs1 += __shfl_xor_sync(0xffffffffu, rs1, 2);
            lrow[mt][0] = lrow[mt][0] * sc0 + rs0;
            lrow[mt][1] = lrow[mt][1] * sc1 + rs1;

#pragma unroll
            for (int j = 0; j < 8; ++j) {
                o[mt][j][0] *= sc0; o[mt][j][1] *= sc0;
                o[mt][j][2] *= sc1; o[mt][j][3] *= sc1;
            }

            // P for this tile to warp-private smem (tf32-rounded)
#pragma unroll
            for (int j = 0; j < 8; ++j) {
                int col = j * 8 + 2 * tig;
                float2 p0 = make_float2(__uint_as_float(cvt_tf32(s[mt][j][0])),
                                        __uint_as_float(cvt_tf32(s[mt][j][1])));
                float2 p1 = make_float2(__uint_as_float(cvt_tf32(s[mt][j][2])),
                                        __uint_as_float(cvt_tf32(s[mt][j][3])));
                *(float2*)&Pw[(mt * 16 + gid) * QP + col]     = p0;
                *(float2*)&Pw[(mt * 16 + gid + 8) * QP + col] = p1;
            }
        }
        __syncwarp();

        // O += P . V — each V fragment feeds both m-tiles
        const uint32_t* Pwu = (const uint32_t*)Pw;
#pragma unroll
        for (int st = 0; st < 8; ++st) {
            int kc = st * 8 + tig;
            uint32_t pa[2][4];
#pragma unroll
            for (int mt = 0; mt < 2; ++mt) {
                pa[mt][0] = Pwu[(mt * 16 + gid) * QP + kc];
                pa[mt][1] = Pwu[(mt * 16 + gid + 8) * QP + kc];
                pa[mt][2] = Pwu[(mt * 16 + gid) * QP + kc + 4];
                pa[mt][3] = Pwu[(mt * 16 + gid + 8) * QP + kc + 4];
            }
#pragma unroll
            for (int j = 0; j < 8; ++j) {
                int dc = j * 8 + gid;
                uint32_t b0 = Vs[kc * VP + dc];
                uint32_t b1 = Vs[(kc + 4) * VP + dc];
                mma_tf32(o[0][j], pa[0], b0, b1);
                mma_tf32(o[1][j], pa[1], b0, b1);
            }
        }
        __syncthreads();
    }

    // Output: reference's flat (B,H,T,d)->(B,T,C) reshape
#pragma unroll
    for (int mt = 0; mt < 2; ++mt) {
        float inv0 = 1.f / lrow[mt][0], inv1 = 1.f / lrow[mt][1];
#pragma unroll
        for (int row = 0; row < 2; ++row) {
            int q     = q0 + wid * 32 + mt * 16 + gid + row * 8;
            int t_out = h * 128 + (q >> 4);
            int cbase = (q & 15) << 6;
            float inv = row ? inv1 : inv0;
#pragma unroll
            for (int j = 0; j < 8; ++j) {
                int dd = j * 8 + 2 * tig;
                float2 v = make_float2(o[mt][j][2 * row] * inv,
                                       o[mt][j][2 * row + 1] * inv);
                *(float2*)(out + (size_t)(b * T_ + t_out) * C_ + cbase + dd) = v;
            }
        }
    }
}

// ---------------------------------------------------------------------------
// Launch (stateless)
// ---------------------------------------------------------------------------
extern "C" void kernel_launch(void* const* d_in, const int* in_sizes, int n_in,
                              void* d_out, int out_size)
{
    const float* x    = (const float*)d_in[0];
    const int*   mask = (const int*)d_in[1];
    const float* W    = (const float*)d_in[2];
    const float* bq   = (const float*)d_in[3];
    float*       out  = (float*)d_out;

    cudaFuncSetAttribute(qkv_gemm_mma,
                         cudaFuncAttributeMaxDynamicSharedMemorySize, GEMM_SMEM_BYTES);
    cudaFuncSetAttribute(flash_attn_mma,
                         cudaFuncAttributeMaxDynamicSharedMemorySize, FLASH_SMEM_BYTES);

    // Pre-round X and W to tf32 (no cvts in the GEMM mainloop).
    round_x_pass<<<2048, 256>>>((const float4*)x);
    round_w_pass<<<1024, 256>>>((const float4*)W);

    dim3 g1(N_TOT / 128, M_TOT / 128);   // 24 x 128
    qkv_gemm_mma<<<g1, 256, GEMM_SMEM_BYTES>>>(bq);

    dim3 g2(T_ / 256, B_ * H_);          // 8 x 128
    flash_attn_mma<<<g2, 256, FLASH_SMEM_BYTES>>>(mask, out);
}